// round 14
// baseline (speedup 1.0000x reference)
#include <cuda_runtime.h>
#include <cuda_fp16.h>
#include <math.h>
#include <float.h>
#include <stdint.h>

typedef unsigned long long ull;

// Problem constants
#define B_      4
#define Q_      75
#define BQ_     300
#define C_      640
#define M_      100
#define J_      25
#define NW_     5
#define MS_     500
#define COLS_   2500
#define ROWSPB_ 7680          // padded rows per b (7500 -> 60*128)
#define CPAD_   2560          // padded cols (2500 -> 10*256)
#define RB_     60            // row blocks of 128
#define CB_     10            // col blocks of 256
#define SEG_    3             // fp16 split: hh, hm, mh
#define NCHUNK_ 30            // 3 segments * 10 k-chunks of 64
#define NSTAGE_ 4
#define NTHR_   512
#define EPS_    1e-8f
#define TEMP_   2.0f

// Static device scratch (no allocation). fp16 component tensors (h, m), k-major.
__device__ __align__(128) __half g_A[(size_t)B_ * 2 * ROWSPB_ * C_]; // 78.6MB
__device__ __align__(128) __half g_B[(size_t)B_ * 2 * CPAD_ * C_];   // 26.2MB
__device__ float g_qinv[BQ_ * M_];
__device__ float g_sinv[B_ * COLS_];
__device__ float g_pcm[(size_t)B_ * ROWSPB_ * CB_ * NW_];
__device__ float g_pgv[(size_t)B_ * ROWSPB_ * CB_];
__device__ int   g_pgi[(size_t)B_ * ROWSPB_ * CB_];
__device__ float g_pred[BQ_ * NW_];

// segment -> component maps: a*b ~= hh + hm + mh  (mm ~ 2^-24, negligible)
__constant__ int c_mapA[SEG_] = {0, 0, 1};
__constant__ int c_mapB[SEG_] = {0, 1, 0};

__device__ __forceinline__ void cpa16(uint32_t dst, const void* src) {
    asm volatile("cp.async.cg.shared.global [%0], [%1], 16;" :: "r"(dst), "l"(src));
}
__device__ __forceinline__ void ldsm4(uint32_t* r, uint32_t addr) {
    asm volatile("ldmatrix.sync.aligned.m8n8.x4.shared.b16 {%0,%1,%2,%3}, [%4];"
        : "=r"(r[0]), "=r"(r[1]), "=r"(r[2]), "=r"(r[3]) : "r"(addr));
}
__device__ __forceinline__ void hmma16(float* d, const uint32_t* a, uint32_t b0, uint32_t b1) {
    asm volatile("mma.sync.aligned.m16n8k16.row.col.f32.f16.f16.f32 "
        "{%0,%1,%2,%3}, {%4,%5,%6,%7}, {%8,%9}, {%0,%1,%2,%3};"
        : "+f"(d[0]), "+f"(d[1]), "+f"(d[2]), "+f"(d[3])
        : "r"(a[0]), "r"(a[1]), "r"(a[2]), "r"(a[3]), "r"(b0), "r"(b1));
}

// ---------------------------------------------------------------------------
// Fused conversion + inverse-norm kernels (one block per (b,q) / (b,j)).
// ---------------------------------------------------------------------------
__global__ __launch_bounds__(256) void convA_k(const float* __restrict__ qry) {
    const int bq = blockIdx.x;
    const int b = bq / Q_, q = bq - b * Q_;
    const int tid = threadIdx.x;
    __shared__ float sT[64][101];
    __shared__ float sSS[M_];

    if (tid < M_) sSS[tid] = 0.f;

    const size_t compStride = (size_t)ROWSPB_ * C_;
    for (int cb64 = 0; cb64 < 10; cb64++) {
        __syncthreads();
        const float* src = qry + ((size_t)bq * C_ + cb64 * 64) * M_;
        for (int e = tid; e < 64 * M_; e += 256)
            sT[e / M_][e % M_] = src[e];
        __syncthreads();

        if (tid < M_) {
            float s = 0.f;
#pragma unroll
            for (int cc = 0; cc < 64; cc++) {
                float v = sT[cc][tid];
                s = fmaf(v, v, s);
            }
            sSS[tid] += s;
        }

        for (int e = tid; e < M_ * 64; e += 256) {
            int m = e >> 6, cc = e & 63;
            float v = sT[cc][m];
            __half h = __float2half_rn(v);
            __half md = __float2half_rn(v - __half2float(h));
            size_t rg = (size_t)q * M_ + m;
            size_t off = ((size_t)(b * 2) * ROWSPB_ + rg) * C_ + (size_t)cb64 * 64 + cc;
            g_A[off] = h;
            g_A[off + compStride] = md;
        }
    }
    __syncthreads();
    if (tid < M_)
        g_qinv[bq * M_ + tid] = 1.0f / (sqrtf(sSS[tid]) + EPS_);
}

__global__ __launch_bounds__(256) void convB_k(const float* __restrict__ sup) {
    const int bj = blockIdx.x;
    const int b = bj / J_, j = bj - b * J_;
    const int tid = threadIdx.x;
    __shared__ float sT[64][101];
    __shared__ float sSS[M_];

    if (tid < M_) sSS[tid] = 0.f;

    const size_t compStride = (size_t)CPAD_ * C_;
    for (int cb64 = 0; cb64 < 10; cb64++) {
        __syncthreads();
        const float* src = sup + ((size_t)bj * C_ + cb64 * 64) * M_;
        for (int e = tid; e < 64 * M_; e += 256)
            sT[e / M_][e % M_] = src[e];
        __syncthreads();

        if (tid < M_) {
            float s = 0.f;
#pragma unroll
            for (int cc = 0; cc < 64; cc++) {
                float v = sT[cc][tid];
                s = fmaf(v, v, s);
            }
            sSS[tid] += s;
        }

        for (int e = tid; e < M_ * 64; e += 256) {
            int m = e >> 6, cc = e & 63;
            float v = sT[cc][m];
            __half h = __float2half_rn(v);
            __half md = __float2half_rn(v - __half2float(h));
            size_t rg = (size_t)j * M_ + m;
            size_t off = ((size_t)(b * 2) * CPAD_ + rg) * C_ + (size_t)cb64 * 64 + cc;
            g_B[off] = h;
            g_B[off + compStride] = md;
        }
    }
    __syncthreads();
    if (tid < M_)
        g_sinv[b * COLS_ + j * M_ + tid] = 1.0f / (sqrtf(sSS[tid]) + EPS_);
}

// ---------------------------------------------------------------------------
// Main HMMA GEMM: CTA tile 128 rows x 256 cols, K_eff = 3*640 fp16.
// 512 threads / 16 warps (2m x 8n), warp tile 64x32 via m16n8k16 -> 4 warps
// per SMSP for issue coverage. 4-stage cp.async pipeline.
// Grid: x in [0,600) swizzled as 15rb x 10cb groups for L2 reuse; z = b.
// ---------------------------------------------------------------------------
extern __shared__ char dynsm[];

__global__ __launch_bounds__(NTHR_, 1) void mma_gemm_k() {
    const int gx = blockIdx.x, b = blockIdx.z;
    const int grp = gx / 150, t150 = gx - grp * 150;
    const int cb = t150 % 10, rb = grp * 15 + t150 / 10;

    const int tid = threadIdx.x, lane = tid & 31, wid = tid >> 5;
    const int wm = wid >> 3, wn = wid & 7;          // 2m x 8n warps
    const int l15 = lane & 15, hi = lane >> 4;

    __shared__ float sSinv[256];

    uintptr_t basep = ((uintptr_t)dynsm + 1023) & ~(uintptr_t)1023;
    const uint32_t aBuf = (uint32_t)__cvta_generic_to_shared((void*)basep);
    uint32_t aA[NSTAGE_], aB[NSTAGE_];
#pragma unroll
    for (int s = 0; s < NSTAGE_; s++) {
        aA[s] = aBuf + (uint32_t)s * 49152u;
        aB[s] = aA[s] + 16384u;
    }
    float* smSD = (float*)basep;   // epilogue D tile, stride 132 floats

    if (tid < 256) {
        int colg = cb * 256 + tid;
        sSinv[tid] = (colg < COLS_) ? g_sinv[b * COLS_ + colg] : 0.f;
    }

    // swizzled k-byte offsets per k16-step (rows are 128B)
    uint32_t kbs[4];
#pragma unroll
    for (int k = 0; k < 4; k++)
        kbs[k] = (uint32_t)((k * 32 + hi * 16) ^ ((lane & 7) * 16));
    uint32_t rowA[4], rowB[2];
#pragma unroll
    for (int mf = 0; mf < 4; mf++) rowA[mf] = (uint32_t)(wm * 64 + mf * 16 + l15) * 128u;
#pragma unroll
    for (int nfp = 0; nfp < 2; nfp++) rowB[nfp] = (uint32_t)(wn * 32 + nfp * 16 + l15) * 128u;

    float d[4][4][4];   // mf x nf(n8) x regs
#pragma unroll
    for (int mf = 0; mf < 4; mf++)
#pragma unroll
        for (int nf = 0; nf < 4; nf++)
#pragma unroll
            for (int r = 0; r < 4; r++) d[mf][nf][r] = 0.f;

    const char* gA = (const char*)g_A;
    const char* gB = (const char*)g_B;

    auto issue = [&](int c) {
        int seg = c / 10, cc = c - seg * 10;
        int p = c & (NSTAGE_ - 1);
        size_t baA = ((size_t)(b * 2 + c_mapA[seg]) * ROWSPB_ + rb * 128) * (C_ * 2)
                     + (size_t)cc * 128;
        size_t baB = ((size_t)(b * 2 + c_mapB[seg]) * CPAD_ + cb * 256) * (C_ * 2)
                     + (size_t)cc * 128;
#pragma unroll
        for (int i = 0; i < 2; i++) {      // A: 128 rows x 8 granules
            int g = tid + NTHR_ * i;
            int r = g >> 3; uint32_t c16 = (uint32_t)(g & 7) * 16;
            cpa16(aA[p] + (uint32_t)r * 128 + (c16 ^ ((uint32_t)(r & 7) * 16)),
                  gA + baA + (size_t)r * (C_ * 2) + c16);
        }
#pragma unroll
        for (int i = 0; i < 4; i++) {      // B: 256 rows x 8 granules
            int g = tid + NTHR_ * i;
            int r = g >> 3; uint32_t c16 = (uint32_t)(g & 7) * 16;
            cpa16(aB[p] + (uint32_t)r * 128 + (c16 ^ ((uint32_t)(r & 7) * 16)),
                  gB + baB + (size_t)r * (C_ * 2) + c16);
        }
        asm volatile("cp.async.commit_group;");
    };

    // prologue: 3 chunks in flight
    issue(0); issue(1); issue(2);

    for (int c = 0; c < NCHUNK_; c++) {
        if (c <= NCHUNK_ - 3)      asm volatile("cp.async.wait_group 2;");
        else if (c == NCHUNK_ - 2) asm volatile("cp.async.wait_group 1;");
        else                       asm volatile("cp.async.wait_group 0;");
        __syncthreads();

        if (c + 3 < NCHUNK_) issue(c + 3);

        const int p = c & (NSTAGE_ - 1);
#pragma unroll
        for (int ks = 0; ks < 4; ks++) {
            uint32_t afr[4][4], bfr[2][4];
#pragma unroll
            for (int mf = 0; mf < 4; mf++) ldsm4(afr[mf], aA[p] + rowA[mf] + kbs[ks]);
#pragma unroll
            for (int nfp = 0; nfp < 2; nfp++) ldsm4(bfr[nfp], aB[p] + rowB[nfp] + kbs[ks]);
#pragma unroll
            for (int mf = 0; mf < 4; mf++)
#pragma unroll
                for (int nf = 0; nf < 4; nf++)
                    hmma16(d[mf][nf], afr[mf],
                           bfr[nf >> 1][nf & 1], bfr[nf >> 1][(nf & 1) + 2]);
        }
    }
    __syncthreads();   // all warps done with last stage before smem reuse

    // ---- epilogue: two 128x128 halves through smem, fused reductions ----
    float cmax[NW_];
#pragma unroll
    for (int w = 0; w < NW_; w++) cmax[w] = -FLT_MAX;
    float gv = -FLT_MAX;
    int gi = 0;

    const int rg = rb * 128 + tid;                 // reducer row (tid<128)
    const bool rvalid = (tid < 128) && (rg < Q_ * M_);
    float qiv = 0.f;
    if (rvalid) {
        int q = rg / M_, m = rg - q * M_;
        qiv = g_qinv[(b * Q_ + q) * M_ + m];
    }

#pragma unroll
    for (int h = 0; h < 2; h++) {
        __syncthreads();
        if ((wn >> 2) == h) {                      // warps wn in [4h, 4h+4)
#pragma unroll
            for (int mf = 0; mf < 4; mf++)
#pragma unroll
                for (int nf = 0; nf < 4; nf++) {
                    int row = wm * 64 + mf * 16 + (lane >> 2);
                    int coll = (wn & 3) * 32 + nf * 8 + (lane & 3) * 2;
                    smSD[row * 132 + coll]       = d[mf][nf][0];
                    smSD[row * 132 + coll + 1]   = d[mf][nf][1];
                    smSD[(row + 8) * 132 + coll]     = d[mf][nf][2];
                    smSD[(row + 8) * 132 + coll + 1] = d[mf][nf][3];
                }
        }
        __syncthreads();
        if (rvalid) {
            for (int cl = 0; cl < 128; cl++) {
                int colg = cb * 256 + h * 128 + cl;
                if (colg < COLS_) {
                    float v = smSD[tid * 132 + cl] * qiv * sSinv[h * 128 + cl];
                    int cls = colg / MS_;
                    if (v > cmax[cls]) cmax[cls] = v;
                    if (v > gv) { gv = v; gi = colg; }   // ascending -> first-index ties
                }
            }
        }
    }

    if (rvalid) {
        size_t pr = ((size_t)b * ROWSPB_ + rg) * CB_ + cb;
#pragma unroll
        for (int w = 0; w < NW_; w++) g_pcm[pr * NW_ + w] = cmax[w];
        g_pgv[pr] = gv;
        g_pgi[pr] = gi;
    }
}

// ---------------------------------------------------------------------------
// Merge partials + mutual-nearest mask + predict (one block per (b,q)).
// ---------------------------------------------------------------------------
__global__ __launch_bounds__(128) void mask_k() {
    const int bq = blockIdx.x;
    const int b = bq / Q_;
    const int tid = threadIdx.x;

    __shared__ float sCm[M_][NW_];
    __shared__ float sDiff[M_];
    __shared__ int   sNear[M_];
    __shared__ float sMask[M_];

    if (tid < M_) {
        int rg = (bq % Q_) * M_ + tid;
        size_t basep = ((size_t)b * ROWSPB_ + rg) * CB_;
        float cm[NW_];
#pragma unroll
        for (int w = 0; w < NW_; w++) cm[w] = -FLT_MAX;
        float gv = -FLT_MAX;
        int gi = 0;
        for (int t = 0; t < CB_; t++) {          // ascending col-block order
            size_t p = basep + t;
#pragma unroll
            for (int w = 0; w < NW_; w++) {
                float v = g_pcm[p * NW_ + w];
                if (v > cm[w]) cm[w] = v;
            }
            float v = g_pgv[p];
            if (v > gv) { gv = v; gi = g_pgi[p]; }
        }
        float m1 = -FLT_MAX, m2 = -FLT_MAX;
#pragma unroll
        for (int w = 0; w < NW_; w++) {
            float v = cm[w];
            if (v > m1) { m2 = m1; m1 = v; }
            else if (v > m2) { m2 = v; }
            sCm[tid][w] = v;
        }
        sDiff[tid] = m1 - m2;
        sNear[tid] = gi;
    }
    __syncthreads();

    if (tid < M_) {
        int slot = sNear[tid];
        float best = -1.0f;
        int idx = -1;
        for (int mp = 0; mp < M_; mp++) {
            float v = (sNear[mp] == slot) ? sDiff[mp] : 0.0f;
            if (v > best) { best = v; idx = mp; }
        }
        sMask[tid] = (idx == tid) ? TEMP_ : 0.0f;
    }
    __syncthreads();

    if (tid < NW_) {
        float p = 0.f;
        for (int m = 0; m < M_; m++)
            p += sCm[m][tid] * sMask[m];
        g_pred[bq * NW_ + tid] = p;
    }
}

// ---------------------------------------------------------------------------
// Loss: log-softmax NLL, deterministic tree reduction.
// ---------------------------------------------------------------------------
__global__ void loss_k(const int* __restrict__ qy, float* __restrict__ out) {
    __shared__ float part[512];
    int t = threadIdx.x;
    float v = 0.f;
    if (t < BQ_) {
        const float* p = g_pred + t * NW_;
        float mx = p[0];
#pragma unroll
        for (int w = 1; w < NW_; w++) mx = fmaxf(mx, p[w]);
        float se = 0.f;
#pragma unroll
        for (int w = 0; w < NW_; w++) se += expf(p[w] - mx);
        float lse = mx + logf(se);
        int y = qy[t];
        v = p[y] - lse;
    }
    part[t] = v;
    __syncthreads();
    for (int s = 256; s > 0; s >>= 1) {
        if (t < s) part[t] += part[t + s];
        __syncthreads();
    }
    if (t == 0) out[0] = -part[0] / (float)BQ_;
}

// ---------------------------------------------------------------------------
extern "C" void kernel_launch(void* const* d_in, const int* in_sizes, int n_in,
                              void* d_out, int out_size)
{
    const float* support_xf = (const float*)d_in[0];   // [4,25,640,100]
    const float* query_xf   = (const float*)d_in[2];   // [4,75,640,100]
    const int*   query_y    = (const int*)d_in[3];     // [4,75]
    float* out = (float*)d_out;

    cudaFuncSetAttribute(mma_gemm_k, cudaFuncAttributeMaxDynamicSharedMemorySize,
                         NSTAGE_ * 49152);

    convA_k<<<BQ_, 256>>>(query_xf);
    convB_k<<<B_ * J_, 256>>>(support_xf);
    mma_gemm_k<<<dim3(600, 1, B_), NTHR_, NSTAGE_ * 49152>>>();
    mask_k<<<BQ_, 128>>>();
    loss_k<<<1, 512>>>(query_y, out);
}

// round 15
// speedup vs baseline: 1.0569x; 1.0569x over previous
#include <cuda_runtime.h>
#include <cuda_fp16.h>
#include <math.h>
#include <float.h>
#include <stdint.h>

typedef unsigned long long ull;

// Problem constants
#define B_      4
#define Q_      75
#define BQ_     300
#define C_      640
#define M_      100
#define J_      25
#define NW_     5
#define MS_     500
#define COLS_   2500
#define ROWS_R  7500          // real rows per b
#define ROWSPB_ 7680          // padded row stride per b
#define CPAD_   2560          // padded cols (2500 -> 10*256)
#define RBLK_   59            // row blocks of 128 (last overlaps: base 7372)
#define CB_     10            // col blocks of 256
#define SEG_    3             // fp16 split: hh, hm, mh
#define NCHUNK_ 30            // 3 segments * 10 k-chunks of 64
#define NSTAGE_ 4
#define SDSTR_  266           // epilogue smem stride (floats): conflict-free
#define EPS_    1e-8f
#define TEMP_   2.0f

// Static device scratch (no allocation). fp16 component tensors (h, m), k-major.
__device__ __align__(128) __half g_A[(size_t)B_ * 2 * ROWSPB_ * C_]; // 78.6MB
__device__ __align__(128) __half g_B[(size_t)B_ * 2 * CPAD_ * C_];   // 26.2MB
__device__ float g_qinv[BQ_ * M_];
__device__ float g_sinv[B_ * COLS_];
__device__ float g_pcm[(size_t)B_ * ROWSPB_ * CB_ * NW_];
__device__ float g_pgv[(size_t)B_ * ROWSPB_ * CB_];
__device__ int   g_pgi[(size_t)B_ * ROWSPB_ * CB_];
__device__ float g_pred[BQ_ * NW_];

// segment -> component maps: a*b ~= hh + hm + mh  (mm ~ 2^-24, negligible)
__constant__ int c_mapA[SEG_] = {0, 0, 1};
__constant__ int c_mapB[SEG_] = {0, 1, 0};

__device__ __forceinline__ void cpa16(uint32_t dst, const void* src) {
    asm volatile("cp.async.cg.shared.global [%0], [%1], 16;" :: "r"(dst), "l"(src));
}
__device__ __forceinline__ void ldsm4(uint32_t* r, uint32_t addr) {
    asm volatile("ldmatrix.sync.aligned.m8n8.x4.shared.b16 {%0,%1,%2,%3}, [%4];"
        : "=r"(r[0]), "=r"(r[1]), "=r"(r[2]), "=r"(r[3]) : "r"(addr));
}
__device__ __forceinline__ void hmma16(float* d, const uint32_t* a, uint32_t b0, uint32_t b1) {
    asm volatile("mma.sync.aligned.m16n8k16.row.col.f32.f16.f16.f32 "
        "{%0,%1,%2,%3}, {%4,%5,%6,%7}, {%8,%9}, {%0,%1,%2,%3};"
        : "+f"(d[0]), "+f"(d[1]), "+f"(d[2]), "+f"(d[3])
        : "r"(a[0]), "r"(a[1]), "r"(a[2]), "r"(a[3]), "r"(b0), "r"(b1));
}

// ---------------------------------------------------------------------------
// Fused conversion + inverse-norm kernels (one block per (b,q) / (b,j)).
// ---------------------------------------------------------------------------
__global__ __launch_bounds__(256) void convA_k(const float* __restrict__ qry) {
    const int bq = blockIdx.x;
    const int b = bq / Q_, q = bq - b * Q_;
    const int tid = threadIdx.x;
    __shared__ float sT[64][101];
    __shared__ float sSS[M_];

    if (tid < M_) sSS[tid] = 0.f;

    const size_t compStride = (size_t)ROWSPB_ * C_;
    for (int cb64 = 0; cb64 < 10; cb64++) {
        __syncthreads();
        const float* src = qry + ((size_t)bq * C_ + cb64 * 64) * M_;
        for (int e = tid; e < 64 * M_; e += 256)
            sT[e / M_][e % M_] = src[e];
        __syncthreads();

        if (tid < M_) {
            float s = 0.f;
#pragma unroll
            for (int cc = 0; cc < 64; cc++) {
                float v = sT[cc][tid];
                s = fmaf(v, v, s);
            }
            sSS[tid] += s;
        }

        for (int e = tid; e < M_ * 64; e += 256) {
            int m = e >> 6, cc = e & 63;
            float v = sT[cc][m];
            __half h = __float2half_rn(v);
            __half md = __float2half_rn(v - __half2float(h));
            size_t rg = (size_t)q * M_ + m;
            size_t off = ((size_t)(b * 2) * ROWSPB_ + rg) * C_ + (size_t)cb64 * 64 + cc;
            g_A[off] = h;
            g_A[off + compStride] = md;
        }
    }
    __syncthreads();
    if (tid < M_)
        g_qinv[bq * M_ + tid] = 1.0f / (sqrtf(sSS[tid]) + EPS_);
}

__global__ __launch_bounds__(256) void convB_k(const float* __restrict__ sup) {
    const int bj = blockIdx.x;
    const int b = bj / J_, j = bj - b * J_;
    const int tid = threadIdx.x;
    __shared__ float sT[64][101];
    __shared__ float sSS[M_];

    if (tid < M_) sSS[tid] = 0.f;

    const size_t compStride = (size_t)CPAD_ * C_;
    for (int cb64 = 0; cb64 < 10; cb64++) {
        __syncthreads();
        const float* src = sup + ((size_t)bj * C_ + cb64 * 64) * M_;
        for (int e = tid; e < 64 * M_; e += 256)
            sT[e / M_][e % M_] = src[e];
        __syncthreads();

        if (tid < M_) {
            float s = 0.f;
#pragma unroll
            for (int cc = 0; cc < 64; cc++) {
                float v = sT[cc][tid];
                s = fmaf(v, v, s);
            }
            sSS[tid] += s;
        }

        for (int e = tid; e < M_ * 64; e += 256) {
            int m = e >> 6, cc = e & 63;
            float v = sT[cc][m];
            __half h = __float2half_rn(v);
            __half md = __float2half_rn(v - __half2float(h));
            size_t rg = (size_t)j * M_ + m;
            size_t off = ((size_t)(b * 2) * CPAD_ + rg) * C_ + (size_t)cb64 * 64 + cc;
            g_B[off] = h;
            g_B[off + compStride] = md;
        }
    }
    __syncthreads();
    if (tid < M_)
        g_sinv[b * COLS_ + j * M_ + tid] = 1.0f / (sqrtf(sSS[tid]) + EPS_);
}

// ---------------------------------------------------------------------------
// Main HMMA GEMM: CTA tile 128 rows x 256 cols, K_eff = 3*640 fp16.
// 8 warps (2m x 4n), warp tile 64x64 via m16n8k16; 4-stage cp.async pipeline
// with ks-level fragment double-buffering. 59 row blocks (last overlaps at
// row 7372 -> no padded-row work, balanced final wave). Single-pass epilogue:
// all 256 threads reduce (2 per row, even/odd col interleave, shfl merge).
// Grid: x in [0,590) swizzled as 15rb x 10cb groups for L2 reuse; z = b.
// ---------------------------------------------------------------------------
extern __shared__ char dynsm[];

__global__ __launch_bounds__(256, 1) void mma_gemm_k() {
    const int gx = blockIdx.x, b = blockIdx.z;
    const int grp = gx / 150, t150 = gx - grp * 150;
    const int cb = t150 % 10, rb = grp * 15 + t150 / 10;
    const int rbase = (rb * 128 <= ROWS_R - 128) ? rb * 128 : (ROWS_R - 128);

    const int tid = threadIdx.x, lane = tid & 31, wid = tid >> 5;
    const int wm = wid >> 2, wn = wid & 3;
    const int l15 = lane & 15, hi = lane >> 4;

    __shared__ float sSinv[256];

    uintptr_t basep = ((uintptr_t)dynsm + 1023) & ~(uintptr_t)1023;
    const uint32_t aBuf = (uint32_t)__cvta_generic_to_shared((void*)basep);
    uint32_t aA[NSTAGE_], aB[NSTAGE_];
#pragma unroll
    for (int s = 0; s < NSTAGE_; s++) {
        aA[s] = aBuf + (uint32_t)s * 49152u;
        aB[s] = aA[s] + 16384u;
    }
    float* smSD = (float*)basep;   // epilogue D tile, stride SDSTR_ floats

    { int colg = cb * 256 + tid;
      sSinv[tid] = (colg < COLS_) ? g_sinv[b * COLS_ + colg] : 0.f; }

    // swizzled k-byte offsets per k16-step (rows are 128B)
    uint32_t kbs[4];
#pragma unroll
    for (int k = 0; k < 4; k++)
        kbs[k] = (uint32_t)((k * 32 + hi * 16) ^ ((lane & 7) * 16));
    uint32_t rowA[4], rowB[4];
#pragma unroll
    for (int mf = 0; mf < 4; mf++) rowA[mf] = (uint32_t)(wm * 64 + mf * 16 + l15) * 128u;
#pragma unroll
    for (int nfp = 0; nfp < 4; nfp++) rowB[nfp] = (uint32_t)(wn * 64 + nfp * 16 + l15) * 128u;

    float d[4][8][4];
#pragma unroll
    for (int mf = 0; mf < 4; mf++)
#pragma unroll
        for (int nf = 0; nf < 8; nf++)
#pragma unroll
            for (int r = 0; r < 4; r++) d[mf][nf][r] = 0.f;

    const char* gA = (const char*)g_A;
    const char* gB = (const char*)g_B;

    auto issue = [&](int c) {
        int seg = c / 10, cc = c - seg * 10;
        int p = c & (NSTAGE_ - 1);
        size_t baA = ((size_t)(b * 2 + c_mapA[seg]) * ROWSPB_ + rbase) * (C_ * 2)
                     + (size_t)cc * 128;
        size_t baB = ((size_t)(b * 2 + c_mapB[seg]) * CPAD_ + cb * 256) * (C_ * 2)
                     + (size_t)cc * 128;
#pragma unroll
        for (int i = 0; i < 4; i++) {      // A: 128 rows x 8 granules
            int g = tid + 256 * i;
            int r = g >> 3; uint32_t c16 = (uint32_t)(g & 7) * 16;
            cpa16(aA[p] + (uint32_t)r * 128 + (c16 ^ ((uint32_t)(r & 7) * 16)),
                  gA + baA + (size_t)r * (C_ * 2) + c16);
        }
#pragma unroll
        for (int i = 0; i < 8; i++) {      // B: 256 rows x 8 granules
            int g = tid + 256 * i;
            int r = g >> 3; uint32_t c16 = (uint32_t)(g & 7) * 16;
            cpa16(aB[p] + (uint32_t)r * 128 + (c16 ^ ((uint32_t)(r & 7) * 16)),
                  gB + baB + (size_t)r * (C_ * 2) + c16);
        }
        asm volatile("cp.async.commit_group;");
    };

    // prologue: 3 chunks in flight
    issue(0); issue(1); issue(2);

    for (int c = 0; c < NCHUNK_; c++) {
        if (c <= NCHUNK_ - 3)      asm volatile("cp.async.wait_group 2;");
        else if (c == NCHUNK_ - 2) asm volatile("cp.async.wait_group 1;");
        else                       asm volatile("cp.async.wait_group 0;");
        __syncthreads();

        if (c + 3 < NCHUNK_) issue(c + 3);

        const int p = c & (NSTAGE_ - 1);

        // ks-pipelined mainloop: preload fragments for ks+1 during hmma of ks
        uint32_t afr[2][4][4], bfr[2][4][4];
#pragma unroll
        for (int mf = 0; mf < 4; mf++) ldsm4(afr[0][mf], aA[p] + rowA[mf] + kbs[0]);
#pragma unroll
        for (int nfp = 0; nfp < 4; nfp++) ldsm4(bfr[0][nfp], aB[p] + rowB[nfp] + kbs[0]);

#pragma unroll
        for (int ks = 0; ks < 4; ks++) {
            const int cur = ks & 1, nx = cur ^ 1;
            if (ks < 3) {
#pragma unroll
                for (int mf = 0; mf < 4; mf++)
                    ldsm4(afr[nx][mf], aA[p] + rowA[mf] + kbs[ks + 1]);
#pragma unroll
                for (int nfp = 0; nfp < 4; nfp++)
                    ldsm4(bfr[nx][nfp], aB[p] + rowB[nfp] + kbs[ks + 1]);
            }
#pragma unroll
            for (int mf = 0; mf < 4; mf++)
#pragma unroll
                for (int nf = 0; nf < 8; nf++)
                    hmma16(d[mf][nf], afr[cur][mf],
                           bfr[cur][nf >> 1][nf & 1], bfr[cur][nf >> 1][(nf & 1) + 2]);
        }
    }
    __syncthreads();   // all warps done with last stage before smem reuse

    // ---- epilogue: single-pass 128x256 through smem, parallel reduction ----
#pragma unroll
    for (int mf = 0; mf < 4; mf++)
#pragma unroll
        for (int nf = 0; nf < 8; nf++) {
            int row = wm * 64 + mf * 16 + (lane >> 2);
            int coll = wn * 64 + nf * 8 + (lane & 3) * 2;
            smSD[row * SDSTR_ + coll]           = d[mf][nf][0];
            smSD[row * SDSTR_ + coll + 1]       = d[mf][nf][1];
            smSD[(row + 8) * SDSTR_ + coll]     = d[mf][nf][2];
            smSD[(row + 8) * SDSTR_ + coll + 1] = d[mf][nf][3];
        }
    __syncthreads();

    {
        const int row = tid >> 1, sub = tid & 1;   // 2 reducers per row
        const int rg = rbase + row;                 // always < ROWS_R
        const int q = rg / M_, m = rg - q * M_;
        const float qiv = g_qinv[(b * Q_ + q) * M_ + m];

        float cmax[NW_];
#pragma unroll
        for (int w = 0; w < NW_; w++) cmax[w] = -FLT_MAX;
        float gv = -FLT_MAX;
        int gi = 0x7FFFFFFF;

        const float* rowp = smSD + row * SDSTR_;
        for (int i = 0; i < 128; i++) {
            int cl = sub + 2 * i;
            int colg = cb * 256 + cl;
            if (colg < COLS_) {
                float v = rowp[cl] * qiv * sSinv[cl];
                int cls = colg / MS_;
                if (v > cmax[cls]) cmax[cls] = v;
                if (v > gv) { gv = v; gi = colg; }   // ascending within sub
            }
        }
        // merge even/odd subs (partition-independent first-index semantics)
#pragma unroll
        for (int w = 0; w < NW_; w++) {
            float o = __shfl_xor_sync(0xFFFFFFFFu, cmax[w], 1);
            cmax[w] = fmaxf(cmax[w], o);
        }
        float ogv = __shfl_xor_sync(0xFFFFFFFFu, gv, 1);
        int   ogi = __shfl_xor_sync(0xFFFFFFFFu, gi, 1);
        if (ogv > gv || (ogv == gv && ogi < gi)) { gv = ogv; gi = ogi; }

        if (sub == 0) {
            size_t pr = ((size_t)b * ROWSPB_ + rg) * CB_ + cb;
#pragma unroll
            for (int w = 0; w < NW_; w++) g_pcm[pr * NW_ + w] = cmax[w];
            g_pgv[pr] = gv;
            g_pgi[pr] = gi;
        }
    }
}

// ---------------------------------------------------------------------------
// Merge partials + mutual-nearest mask + predict (one block per (b,q)).
// ---------------------------------------------------------------------------
__global__ __launch_bounds__(128) void mask_k() {
    const int bq = blockIdx.x;
    const int b = bq / Q_;
    const int tid = threadIdx.x;

    __shared__ float sCm[M_][NW_];
    __shared__ float sDiff[M_];
    __shared__ int   sNear[M_];
    __shared__ float sMask[M_];

    if (tid < M_) {
        int rg = (bq % Q_) * M_ + tid;
        size_t basep = ((size_t)b * ROWSPB_ + rg) * CB_;
        float cm[NW_];
#pragma unroll
        for (int w = 0; w < NW_; w++) cm[w] = -FLT_MAX;
        float gv = -FLT_MAX;
        int gi = 0;
        for (int t = 0; t < CB_; t++) {          // ascending col-block order
            size_t p = basep + t;
#pragma unroll
            for (int w = 0; w < NW_; w++) {
                float v = g_pcm[p * NW_ + w];
                if (v > cm[w]) cm[w] = v;
            }
            float v = g_pgv[p];
            if (v > gv) { gv = v; gi = g_pgi[p]; }
        }
        float m1 = -FLT_MAX, m2 = -FLT_MAX;
#pragma unroll
        for (int w = 0; w < NW_; w++) {
            float v = cm[w];
            if (v > m1) { m2 = m1; m1 = v; }
            else if (v > m2) { m2 = v; }
            sCm[tid][w] = v;
        }
        sDiff[tid] = m1 - m2;
        sNear[tid] = gi;
    }
    __syncthreads();

    if (tid < M_) {
        int slot = sNear[tid];
        float best = -1.0f;
        int idx = -1;
        for (int mp = 0; mp < M_; mp++) {
            float v = (sNear[mp] == slot) ? sDiff[mp] : 0.0f;
            if (v > best) { best = v; idx = mp; }
        }
        sMask[tid] = (idx == tid) ? TEMP_ : 0.0f;
    }
    __syncthreads();

    if (tid < NW_) {
        float p = 0.f;
        for (int m = 0; m < M_; m++)
            p += sCm[m][tid] * sMask[m];
        g_pred[bq * NW_ + tid] = p;
    }
}

// ---------------------------------------------------------------------------
// Loss: log-softmax NLL, deterministic tree reduction.
// ---------------------------------------------------------------------------
__global__ void loss_k(const int* __restrict__ qy, float* __restrict__ out) {
    __shared__ float part[512];
    int t = threadIdx.x;
    float v = 0.f;
    if (t < BQ_) {
        const float* p = g_pred + t * NW_;
        float mx = p[0];
#pragma unroll
        for (int w = 1; w < NW_; w++) mx = fmaxf(mx, p[w]);
        float se = 0.f;
#pragma unroll
        for (int w = 0; w < NW_; w++) se += expf(p[w] - mx);
        float lse = mx + logf(se);
        int y = qy[t];
        v = p[y] - lse;
    }
    part[t] = v;
    __syncthreads();
    for (int s = 256; s > 0; s >>= 1) {
        if (t < s) part[t] += part[t + s];
        __syncthreads();
    }
    if (t == 0) out[0] = -part[0] / (float)BQ_;
}

// ---------------------------------------------------------------------------
extern "C" void kernel_launch(void* const* d_in, const int* in_sizes, int n_in,
                              void* d_out, int out_size)
{
    const float* support_xf = (const float*)d_in[0];   // [4,25,640,100]
    const float* query_xf   = (const float*)d_in[2];   // [4,75,640,100]
    const int*   query_y    = (const int*)d_in[3];     // [4,75]
    float* out = (float*)d_out;

    cudaFuncSetAttribute(mma_gemm_k, cudaFuncAttributeMaxDynamicSharedMemorySize,
                         NSTAGE_ * 49152);

    convA_k<<<BQ_, 256>>>(query_xf);
    convB_k<<<B_ * J_, 256>>>(support_xf);
    mma_gemm_k<<<dim3(590, 1, B_), 256, NSTAGE_ * 49152>>>();
    mask_k<<<BQ_, 128>>>();
    loss_k<<<1, 512>>>(query_y, out);
}

// round 16
// speedup vs baseline: 1.2292x; 1.1630x over previous
#include <cuda_runtime.h>
#include <cuda_fp16.h>
#include <math.h>
#include <float.h>
#include <stdint.h>

typedef unsigned long long ull;

// Problem constants
#define B_      4
#define Q_      75
#define BQ_     300
#define C_      640
#define M_      100
#define J_      25
#define NW_     5
#define MS_     500
#define COLS_   2500
#define ROWS_R  7500          // real rows per b
#define ROWSPB_ 7680          // padded row stride per b
#define CPAD_   2560          // padded cols (2500 -> 10*256)
#define CB_     10            // col blocks of 256
#define SEG_    3             // fp16 split: hh, hm, mh
#define NCHUNK_ 30            // 3 segments * 10 k-chunks of 64
#define NSTAGE_ 4
#define SDSTR_  260           // epilogue smem stride (floats), 16B-aligned rows
#define EPS_    1e-8f
#define TEMP_   2.0f

// Static device scratch (no allocation). fp16 component tensors (h, m), k-major.
__device__ __align__(128) __half g_A[(size_t)B_ * 2 * ROWSPB_ * C_]; // 78.6MB
__device__ __align__(128) __half g_B[(size_t)B_ * 2 * CPAD_ * C_];   // 26.2MB
__device__ float g_qinv[BQ_ * M_];
__device__ float g_sinv[B_ * COLS_];
__device__ float g_pcm[(size_t)B_ * ROWSPB_ * CB_ * NW_];
__device__ float g_pgv[(size_t)B_ * ROWSPB_ * CB_];
__device__ int   g_pgi[(size_t)B_ * ROWSPB_ * CB_];
__device__ float g_pred[BQ_ * NW_];
__device__ int   g_cnt;      // zero-initialized; self-resetting per replay

// segment -> component maps: a*b ~= hh + hm + mh  (mm ~ 2^-24, negligible)
__constant__ int c_mapA[SEG_] = {0, 0, 1};
__constant__ int c_mapB[SEG_] = {0, 1, 0};

__device__ __forceinline__ void cpa16(uint32_t dst, const void* src) {
    asm volatile("cp.async.cg.shared.global [%0], [%1], 16;" :: "r"(dst), "l"(src));
}
__device__ __forceinline__ void ldsm4(uint32_t* r, uint32_t addr) {
    asm volatile("ldmatrix.sync.aligned.m8n8.x4.shared.b16 {%0,%1,%2,%3}, [%4];"
        : "=r"(r[0]), "=r"(r[1]), "=r"(r[2]), "=r"(r[3]) : "r"(addr));
}
__device__ __forceinline__ void hmma16(float* d, const uint32_t* a, uint32_t b0, uint32_t b1) {
    asm volatile("mma.sync.aligned.m16n8k16.row.col.f32.f16.f16.f32 "
        "{%0,%1,%2,%3}, {%4,%5,%6,%7}, {%8,%9}, {%0,%1,%2,%3};"
        : "+f"(d[0]), "+f"(d[1]), "+f"(d[2]), "+f"(d[3])
        : "r"(a[0]), "r"(a[1]), "r"(a[2]), "r"(a[3]), "r"(b0), "r"(b1));
}

// ---------------------------------------------------------------------------
// Merged conversion + inverse-norm kernel. Blocks [0,300): query (A side);
// blocks [300,400): support (B side). Runs both concurrently in one launch.
// ---------------------------------------------------------------------------
__global__ __launch_bounds__(256) void convAB_k(const float* __restrict__ qry,
                                                const float* __restrict__ sup) {
    const int tid = threadIdx.x;
    __shared__ float sT[64][101];
    __shared__ float sSS[M_];

    if (tid < M_) sSS[tid] = 0.f;

    if (blockIdx.x < BQ_) {
        const int bq = blockIdx.x;
        const int b = bq / Q_, q = bq - b * Q_;
        const size_t compStride = (size_t)ROWSPB_ * C_;
        for (int cb64 = 0; cb64 < 10; cb64++) {
            __syncthreads();
            const float* src = qry + ((size_t)bq * C_ + cb64 * 64) * M_;
            for (int e = tid; e < 64 * M_; e += 256)
                sT[e / M_][e % M_] = src[e];
            __syncthreads();

            if (tid < M_) {
                float s = 0.f;
#pragma unroll
                for (int cc = 0; cc < 64; cc++) {
                    float v = sT[cc][tid];
                    s = fmaf(v, v, s);
                }
                sSS[tid] += s;
            }
            for (int e = tid; e < M_ * 64; e += 256) {
                int m = e >> 6, cc = e & 63;
                float v = sT[cc][m];
                __half h = __float2half_rn(v);
                __half md = __float2half_rn(v - __half2float(h));
                size_t rg = (size_t)q * M_ + m;
                size_t off = ((size_t)(b * 2) * ROWSPB_ + rg) * C_ + (size_t)cb64 * 64 + cc;
                g_A[off] = h;
                g_A[off + compStride] = md;
            }
        }
        __syncthreads();
        if (tid < M_)
            g_qinv[bq * M_ + tid] = 1.0f / (sqrtf(sSS[tid]) + EPS_);
    } else {
        const int bj = blockIdx.x - BQ_;
        const int b = bj / J_, j = bj - b * J_;
        const size_t compStride = (size_t)CPAD_ * C_;
        for (int cb64 = 0; cb64 < 10; cb64++) {
            __syncthreads();
            const float* src = sup + ((size_t)bj * C_ + cb64 * 64) * M_;
            for (int e = tid; e < 64 * M_; e += 256)
                sT[e / M_][e % M_] = src[e];
            __syncthreads();

            if (tid < M_) {
                float s = 0.f;
#pragma unroll
                for (int cc = 0; cc < 64; cc++) {
                    float v = sT[cc][tid];
                    s = fmaf(v, v, s);
                }
                sSS[tid] += s;
            }
            for (int e = tid; e < M_ * 64; e += 256) {
                int m = e >> 6, cc = e & 63;
                float v = sT[cc][m];
                __half h = __float2half_rn(v);
                __half md = __float2half_rn(v - __half2float(h));
                size_t rg = (size_t)j * M_ + m;
                size_t off = ((size_t)(b * 2) * CPAD_ + rg) * C_ + (size_t)cb64 * 64 + cc;
                g_B[off] = h;
                g_B[off + compStride] = md;
            }
        }
        __syncthreads();
        if (tid < M_)
            g_sinv[b * COLS_ + j * M_ + tid] = 1.0f / (sqrtf(sSS[tid]) + EPS_);
    }
}

// ---------------------------------------------------------------------------
// Main HMMA GEMM: CTA tile 128 rows x 256 cols, K_eff = 3*640 fp16.
// 8 warps (2m x 4n), warp tile 64x64 via m16n8k16; 4-stage cp.async pipeline
// with ks-level fragment double-buffering. 59 row blocks (last overlaps at
// row 7372). Single-pass epilogue: 2 reducers/row over contiguous 128-col
// halves, float4 groups (class id constant per aligned 4-group), shfl merge.
// Grid: x in [0,590) swizzled as 15rb x 10cb groups for L2 reuse; z = b.
// ---------------------------------------------------------------------------
extern __shared__ char dynsm[];

__global__ __launch_bounds__(256, 1) void mma_gemm_k() {
    const int gx = blockIdx.x, b = blockIdx.z;
    const int grp = gx / 150, t150 = gx - grp * 150;
    const int cb = t150 % 10, rb = grp * 15 + t150 / 10;
    const int rbase = (rb * 128 <= ROWS_R - 128) ? rb * 128 : (ROWS_R - 128);

    const int tid = threadIdx.x, lane = tid & 31, wid = tid >> 5;
    const int wm = wid >> 2, wn = wid & 3;
    const int l15 = lane & 15, hi = lane >> 4;

    __shared__ float sSinv[256];

    uintptr_t basep = ((uintptr_t)dynsm + 1023) & ~(uintptr_t)1023;
    const uint32_t aBuf = (uint32_t)__cvta_generic_to_shared((void*)basep);
    uint32_t aA[NSTAGE_], aB[NSTAGE_];
#pragma unroll
    for (int s = 0; s < NSTAGE_; s++) {
        aA[s] = aBuf + (uint32_t)s * 49152u;
        aB[s] = aA[s] + 16384u;
    }
    float* smSD = (float*)basep;   // epilogue D tile, stride SDSTR_ floats

    { int colg = cb * 256 + tid;
      sSinv[tid] = (colg < COLS_) ? g_sinv[b * COLS_ + colg] : 0.f; }

    // swizzled k-byte offsets per k16-step (rows are 128B)
    uint32_t kbs[4];
#pragma unroll
    for (int k = 0; k < 4; k++)
        kbs[k] = (uint32_t)((k * 32 + hi * 16) ^ ((lane & 7) * 16));
    uint32_t rowA[4], rowB[4];
#pragma unroll
    for (int mf = 0; mf < 4; mf++) rowA[mf] = (uint32_t)(wm * 64 + mf * 16 + l15) * 128u;
#pragma unroll
    for (int nfp = 0; nfp < 4; nfp++) rowB[nfp] = (uint32_t)(wn * 64 + nfp * 16 + l15) * 128u;

    float d[4][8][4];
#pragma unroll
    for (int mf = 0; mf < 4; mf++)
#pragma unroll
        for (int nf = 0; nf < 8; nf++)
#pragma unroll
            for (int r = 0; r < 4; r++) d[mf][nf][r] = 0.f;

    const char* gA = (const char*)g_A;
    const char* gB = (const char*)g_B;

    auto issue = [&](int c) {
        int seg = c / 10, cc = c - seg * 10;
        int p = c & (NSTAGE_ - 1);
        size_t baA = ((size_t)(b * 2 + c_mapA[seg]) * ROWSPB_ + rbase) * (C_ * 2)
                     + (size_t)cc * 128;
        size_t baB = ((size_t)(b * 2 + c_mapB[seg]) * CPAD_ + cb * 256) * (C_ * 2)
                     + (size_t)cc * 128;
#pragma unroll
        for (int i = 0; i < 4; i++) {      // A: 128 rows x 8 granules
            int g = tid + 256 * i;
            int r = g >> 3; uint32_t c16 = (uint32_t)(g & 7) * 16;
            cpa16(aA[p] + (uint32_t)r * 128 + (c16 ^ ((uint32_t)(r & 7) * 16)),
                  gA + baA + (size_t)r * (C_ * 2) + c16);
        }
#pragma unroll
        for (int i = 0; i < 8; i++) {      // B: 256 rows x 8 granules
            int g = tid + 256 * i;
            int r = g >> 3; uint32_t c16 = (uint32_t)(g & 7) * 16;
            cpa16(aB[p] + (uint32_t)r * 128 + (c16 ^ ((uint32_t)(r & 7) * 16)),
                  gB + baB + (size_t)r * (C_ * 2) + c16);
        }
        asm volatile("cp.async.commit_group;");
    };

    // prologue: 3 chunks in flight
    issue(0); issue(1); issue(2);

    for (int c = 0; c < NCHUNK_; c++) {
        if (c <= NCHUNK_ - 3)      asm volatile("cp.async.wait_group 2;");
        else if (c == NCHUNK_ - 2) asm volatile("cp.async.wait_group 1;");
        else                       asm volatile("cp.async.wait_group 0;");
        __syncthreads();

        if (c + 3 < NCHUNK_) issue(c + 3);

        const int p = c & (NSTAGE_ - 1);

        // ks-pipelined mainloop: preload fragments for ks+1 during hmma of ks
        uint32_t afr[2][4][4], bfr[2][4][4];
#pragma unroll
        for (int mf = 0; mf < 4; mf++) ldsm4(afr[0][mf], aA[p] + rowA[mf] + kbs[0]);
#pragma unroll
        for (int nfp = 0; nfp < 4; nfp++) ldsm4(bfr[0][nfp], aB[p] + rowB[nfp] + kbs[0]);

#pragma unroll
        for (int ks = 0; ks < 4; ks++) {
            const int cur = ks & 1, nx = cur ^ 1;
            if (ks < 3) {
#pragma unroll
                for (int mf = 0; mf < 4; mf++)
                    ldsm4(afr[nx][mf], aA[p] + rowA[mf] + kbs[ks + 1]);
#pragma unroll
                for (int nfp = 0; nfp < 4; nfp++)
                    ldsm4(bfr[nx][nfp], aB[p] + rowB[nfp] + kbs[ks + 1]);
            }
#pragma unroll
            for (int mf = 0; mf < 4; mf++)
#pragma unroll
                for (int nf = 0; nf < 8; nf++)
                    hmma16(d[mf][nf], afr[cur][mf],
                           bfr[cur][nf >> 1][nf & 1], bfr[cur][nf >> 1][(nf & 1) + 2]);
        }
    }
    __syncthreads();   // all warps done with last stage before smem reuse

    // ---- epilogue: single-pass 128x256 through smem, parallel reduction ----
#pragma unroll
    for (int mf = 0; mf < 4; mf++)
#pragma unroll
        for (int nf = 0; nf < 8; nf++) {
            int row = wm * 64 + mf * 16 + (lane >> 2);
            int coll = wn * 64 + nf * 8 + (lane & 3) * 2;
            smSD[row * SDSTR_ + coll]           = d[mf][nf][0];
            smSD[row * SDSTR_ + coll + 1]       = d[mf][nf][1];
            smSD[(row + 8) * SDSTR_ + coll]     = d[mf][nf][2];
            smSD[(row + 8) * SDSTR_ + coll + 1] = d[mf][nf][3];
        }
    __syncthreads();

    {
        const int row = tid >> 1, sub = tid & 1;   // 2 reducers per row, halves
        const int rg = rbase + row;                 // always < ROWS_R
        const int q = rg / M_, m = rg - q * M_;
        const float qiv = g_qinv[(b * Q_ + q) * M_ + m];

        float cmax[NW_];
#pragma unroll
        for (int w = 0; w < NW_; w++) cmax[w] = -FLT_MAX;
        float gv = -FLT_MAX;
        int gi = 0x7FFFFFFF;

        const float* rowp = smSD + row * SDSTR_ + sub * 128;
        const float* sinp = sSinv + sub * 128;
        const int colg0 = cb * 256 + sub * 128;

        // 32 float4 groups; 500 and 2500 are multiples of 4 -> class id and
        // validity are constant within each aligned group.
        for (int i = 0; i < 32; i++) {
            int colg = colg0 + 4 * i;
            if (colg < COLS_) {
                float4 vv = *(const float4*)(rowp + 4 * i);
                float4 sv = *(const float4*)(sinp + 4 * i);
                float v0 = vv.x * qiv * sv.x;
                float v1 = vv.y * qiv * sv.y;
                float v2 = vv.z * qiv * sv.z;
                float v3 = vv.w * qiv * sv.w;
                float bv = v0; int bo = 0;
                if (v1 > bv) { bv = v1; bo = 1; }
                if (v2 > bv) { bv = v2; bo = 2; }
                if (v3 > bv) { bv = v3; bo = 3; }
                int cls = colg / MS_;
                if (bv > cmax[cls]) cmax[cls] = bv;
                if (bv > gv) { gv = bv; gi = colg + bo; }  // ascending scan
            }
        }
        // merge halves (partition-independent first-index semantics)
#pragma unroll
        for (int w = 0; w < NW_; w++) {
            float o = __shfl_xor_sync(0xFFFFFFFFu, cmax[w], 1);
            cmax[w] = fmaxf(cmax[w], o);
        }
        float ogv = __shfl_xor_sync(0xFFFFFFFFu, gv, 1);
        int   ogi = __shfl_xor_sync(0xFFFFFFFFu, gi, 1);
        if (ogv > gv || (ogv == gv && ogi < gi)) { gv = ogv; gi = ogi; }

        if (sub == 0) {
            size_t pr = ((size_t)b * ROWSPB_ + rg) * CB_ + cb;
#pragma unroll
            for (int w = 0; w < NW_; w++) g_pcm[pr * NW_ + w] = cmax[w];
            g_pgv[pr] = gv;
            g_pgi[pr] = gi;
        }
    }
}

// ---------------------------------------------------------------------------
// Merge partials + mutual-nearest mask + predict (one block per (b,q)),
// with the final loss fused via the last-block threadfence pattern.
// ---------------------------------------------------------------------------
__global__ __launch_bounds__(128) void mask_k(const int* __restrict__ qy,
                                              float* __restrict__ out) {
    const int bq = blockIdx.x;
    const int b = bq / Q_;
    const int tid = threadIdx.x;

    __shared__ float sCm[M_][NW_];
    __shared__ float sDiff[M_];
    __shared__ int   sNear[M_];
    __shared__ float sMask[M_];
    __shared__ int   sLast;
    __shared__ float sPart[128];

    if (tid < M_) {
        int rg = (bq % Q_) * M_ + tid;
        size_t basep = ((size_t)b * ROWSPB_ + rg) * CB_;
        float cm[NW_];
#pragma unroll
        for (int w = 0; w < NW_; w++) cm[w] = -FLT_MAX;
        float gv = -FLT_MAX;
        int gi = 0;
        for (int t = 0; t < CB_; t++) {          // ascending col-block order
            size_t p = basep + t;
#pragma unroll
            for (int w = 0; w < NW_; w++) {
                float v = g_pcm[p * NW_ + w];
                if (v > cm[w]) cm[w] = v;
            }
            float v = g_pgv[p];
            if (v > gv) { gv = v; gi = g_pgi[p]; }
        }
        float m1 = -FLT_MAX, m2 = -FLT_MAX;
#pragma unroll
        for (int w = 0; w < NW_; w++) {
            float v = cm[w];
            if (v > m1) { m2 = m1; m1 = v; }
            else if (v > m2) { m2 = v; }
            sCm[tid][w] = v;
        }
        sDiff[tid] = m1 - m2;
        sNear[tid] = gi;
    }
    __syncthreads();

    if (tid < M_) {
        int slot = sNear[tid];
        float best = -1.0f;
        int idx = -1;
        for (int mp = 0; mp < M_; mp++) {
            float v = (sNear[mp] == slot) ? sDiff[mp] : 0.0f;
            if (v > best) { best = v; idx = mp; }
        }
        sMask[tid] = (idx == tid) ? TEMP_ : 0.0f;
    }
    __syncthreads();

    if (tid < NW_) {
        float p = 0.f;
        for (int m = 0; m < M_; m++)
            p += sCm[m][tid] * sMask[m];
        g_pred[bq * NW_ + tid] = p;
    }

    // ---- last block computes the loss (deterministic tree reduction) ----
    __threadfence();
    __syncthreads();
    if (tid == 0) {
        int c = atomicAdd(&g_cnt, 1);
        sLast = (c == BQ_ - 1) ? 1 : 0;
    }
    __syncthreads();
    if (sLast) {
        __threadfence();
        float v = 0.f;
        for (int t = tid; t < BQ_; t += 128) {     // fixed order per thread
            const float* p = g_pred + t * NW_;
            float mx = p[0];
#pragma unroll
            for (int w = 1; w < NW_; w++) mx = fmaxf(mx, p[w]);
            float se = 0.f;
#pragma unroll
            for (int w = 0; w < NW_; w++) se += expf(p[w] - mx);
            float lse = mx + logf(se);
            v += p[qy[t]] - lse;
        }
        sPart[tid] = v;
        __syncthreads();
        for (int s = 64; s > 0; s >>= 1) {
            if (tid < s) sPart[tid] += sPart[tid + s];
            __syncthreads();
        }
        if (tid == 0) {
            out[0] = -sPart[0] / (float)BQ_;
            g_cnt = 0;                              // reset for next replay
        }
    }
}

// ---------------------------------------------------------------------------
extern "C" void kernel_launch(void* const* d_in, const int* in_sizes, int n_in,
                              void* d_out, int out_size)
{
    const float* support_xf = (const float*)d_in[0];   // [4,25,640,100]
    const float* query_xf   = (const float*)d_in[2];   // [4,75,640,100]
    const int*   query_y    = (const int*)d_in[3];     // [4,75]
    float* out = (float*)d_out;

    cudaFuncSetAttribute(mma_gemm_k, cudaFuncAttributeMaxDynamicSharedMemorySize,
                         NSTAGE_ * 49152);

    convAB_k<<<BQ_ + B_ * J_, 256>>>(query_xf, support_xf);
    mma_gemm_k<<<dim3(590, 1, B_), 256, NSTAGE_ * 49152>>>();
    mask_k<<<BQ_, 128>>>(query_y, out);
}

// round 17
// speedup vs baseline: 1.2593x; 1.0245x over previous
#include <cuda_runtime.h>
#include <cuda_fp16.h>
#include <math.h>
#include <float.h>
#include <stdint.h>

typedef unsigned long long ull;

// Problem constants
#define B_      4
#define Q_      75
#define BQ_     300
#define C_      640
#define M_      100
#define J_      25
#define NW_     5
#define MS_     500
#define COLS_   2500
#define ROWS_R  7500          // real rows per b
#define ROWSPB_ 7680          // padded row stride per b
#define CPAD_   2560          // padded cols (2500 -> 10*256)
#define CB_     10            // col blocks of 256
#define SEG_    3             // fp16 split: hh, hm, mh
#define NCHUNK_ 30            // 3 segments * 10 k-chunks of 64
#define NSTAGE_ 4
#define SDSTR_  260           // epilogue smem stride (floats), 16B-aligned rows
#define NENT_   400           // 300 query + 100 support entities
#define EPS_    1e-8f
#define TEMP_   2.0f

// Static device scratch (no allocation). fp16 component tensors (h, m), k-major.
__device__ __align__(128) __half g_A[(size_t)B_ * 2 * ROWSPB_ * C_]; // 78.6MB
__device__ __align__(128) __half g_B[(size_t)B_ * 2 * CPAD_ * C_];   // 26.2MB
__device__ float g_nss[NENT_ * 10 * M_];   // per-(entity, cb64) norm partials
__device__ float g_qinv[BQ_ * M_];
__device__ float g_sinv[B_ * COLS_];
__device__ float g_pcm[(size_t)B_ * ROWSPB_ * CB_ * NW_];
__device__ float g_pgv[(size_t)B_ * ROWSPB_ * CB_];
__device__ int   g_pgi[(size_t)B_ * ROWSPB_ * CB_];
__device__ float g_pred[BQ_ * NW_];
__device__ int   g_cnt;      // zero-initialized; self-resetting per replay

// segment -> component maps: a*b ~= hh + hm + mh  (mm ~ 2^-24, negligible)
__constant__ int c_mapA[SEG_] = {0, 0, 1};
__constant__ int c_mapB[SEG_] = {0, 1, 0};

__device__ __forceinline__ void cpa16(uint32_t dst, const void* src) {
    asm volatile("cp.async.cg.shared.global [%0], [%1], 16;" :: "r"(dst), "l"(src));
}
__device__ __forceinline__ void ldsm4(uint32_t* r, uint32_t addr) {
    asm volatile("ldmatrix.sync.aligned.m8n8.x4.shared.b16 {%0,%1,%2,%3}, [%4];"
        : "=r"(r[0]), "=r"(r[1]), "=r"(r[2]), "=r"(r[3]) : "r"(addr));
}
__device__ __forceinline__ void hmma16(float* d, const uint32_t* a, uint32_t b0, uint32_t b1) {
    asm volatile("mma.sync.aligned.m16n8k16.row.col.f32.f16.f16.f32 "
        "{%0,%1,%2,%3}, {%4,%5,%6,%7}, {%8,%9}, {%0,%1,%2,%3};"
        : "+f"(d[0]), "+f"(d[1]), "+f"(d[2]), "+f"(d[3])
        : "r"(a[0]), "r"(a[1]), "r"(a[2]), "r"(a[3]), "r"(b0), "r"(b1));
}

// ---------------------------------------------------------------------------
// Wide-grid conversion kernel: one CTA per (cb64, entity).
// Entities [0,300): query (A side); [300,400): support (B side).
// Writes fp16 (h, m) components + per-(entity, cb64) norm partials.
// ---------------------------------------------------------------------------
__global__ __launch_bounds__(256) void convAB_k(const float* __restrict__ qry,
                                                const float* __restrict__ sup) {
    const int cb64 = blockIdx.x;
    const int ent  = blockIdx.y;
    const int tid  = threadIdx.x;
    __shared__ float sT[64][101];

    if (ent < BQ_) {
        const int bq = ent;
        const int b = bq / Q_, q = bq - b * Q_;
        const float* src = qry + ((size_t)bq * C_ + cb64 * 64) * M_;
        for (int e = tid; e < 64 * M_; e += 256)
            sT[e / M_][e % M_] = src[e];           // coalesced (m contiguous)
        __syncthreads();

        if (tid < M_) {
            float s = 0.f;
#pragma unroll
            for (int cc = 0; cc < 64; cc++) {
                float v = sT[cc][tid];
                s = fmaf(v, v, s);
            }
            g_nss[(ent * 10 + cb64) * M_ + tid] = s;
        }

        const size_t compStride = (size_t)ROWSPB_ * C_;
        for (int e = tid; e < M_ * 64; e += 256) {
            int m = e >> 6, cc = e & 63;
            float v = sT[cc][m];
            __half h = __float2half_rn(v);
            __half md = __float2half_rn(v - __half2float(h));
            size_t rg = (size_t)q * M_ + m;
            size_t off = ((size_t)(b * 2) * ROWSPB_ + rg) * C_ + (size_t)cb64 * 64 + cc;
            g_A[off] = h;
            g_A[off + compStride] = md;
        }
    } else {
        const int bj = ent - BQ_;
        const int b = bj / J_, j = bj - b * J_;
        const float* src = sup + ((size_t)bj * C_ + cb64 * 64) * M_;
        for (int e = tid; e < 64 * M_; e += 256)
            sT[e / M_][e % M_] = src[e];
        __syncthreads();

        if (tid < M_) {
            float s = 0.f;
#pragma unroll
            for (int cc = 0; cc < 64; cc++) {
                float v = sT[cc][tid];
                s = fmaf(v, v, s);
            }
            g_nss[(ent * 10 + cb64) * M_ + tid] = s;
        }

        const size_t compStride = (size_t)CPAD_ * C_;
        for (int e = tid; e < M_ * 64; e += 256) {
            int m = e >> 6, cc = e & 63;
            float v = sT[cc][m];
            __half h = __float2half_rn(v);
            __half md = __float2half_rn(v - __half2float(h));
            size_t rg = (size_t)j * M_ + m;
            size_t off = ((size_t)(b * 2) * CPAD_ + rg) * C_ + (size_t)cb64 * 64 + cc;
            g_B[off] = h;
            g_B[off + compStride] = md;
        }
    }
}

// ---------------------------------------------------------------------------
// Norm finalize: fold the 10 cb64 partials per (entity, m) in ascending
// order (bit-identical to the previous serial accumulation).
// ---------------------------------------------------------------------------
__global__ __launch_bounds__(128) void normfin_k() {
    const int ent = blockIdx.x;
    const int t = threadIdx.x;
    if (t >= M_) return;
    float s = 0.f;
    for (int cb64 = 0; cb64 < 10; cb64++)
        s += g_nss[(ent * 10 + cb64) * M_ + t];
    float inv = 1.0f / (sqrtf(s) + EPS_);
    if (ent < BQ_) {
        g_qinv[ent * M_ + t] = inv;
    } else {
        int bj = ent - BQ_;
        int b = bj / J_, j = bj - b * J_;
        g_sinv[b * COLS_ + j * M_ + t] = inv;
    }
}

// ---------------------------------------------------------------------------
// Main HMMA GEMM: CTA tile 128 rows x 256 cols, K_eff = 3*640 fp16.
// 8 warps (2m x 4n), warp tile 64x64 via m16n8k16; 4-stage cp.async pipeline
// with ks-level fragment double-buffering. 59 row blocks (last overlaps at
// row 7372). Single-pass epilogue: 2 reducers/row over contiguous 128-col
// halves, float4 groups, shfl merge.
// Grid: x in [0,590) swizzled as 15rb x 10cb groups for L2 reuse; z = b.
// ---------------------------------------------------------------------------
extern __shared__ char dynsm[];

__global__ __launch_bounds__(256, 1) void mma_gemm_k() {
    const int gx = blockIdx.x, b = blockIdx.z;
    const int grp = gx / 150, t150 = gx - grp * 150;
    const int cb = t150 % 10, rb = grp * 15 + t150 / 10;
    const int rbase = (rb * 128 <= ROWS_R - 128) ? rb * 128 : (ROWS_R - 128);

    const int tid = threadIdx.x, lane = tid & 31, wid = tid >> 5;
    const int wm = wid >> 2, wn = wid & 3;
    const int l15 = lane & 15, hi = lane >> 4;

    __shared__ float sSinv[256];

    uintptr_t basep = ((uintptr_t)dynsm + 1023) & ~(uintptr_t)1023;
    const uint32_t aBuf = (uint32_t)__cvta_generic_to_shared((void*)basep);
    uint32_t aA[NSTAGE_], aB[NSTAGE_];
#pragma unroll
    for (int s = 0; s < NSTAGE_; s++) {
        aA[s] = aBuf + (uint32_t)s * 49152u;
        aB[s] = aA[s] + 16384u;
    }
    float* smSD = (float*)basep;   // epilogue D tile, stride SDSTR_ floats

    { int colg = cb * 256 + tid;
      sSinv[tid] = (colg < COLS_) ? g_sinv[b * COLS_ + colg] : 0.f; }

    // swizzled k-byte offsets per k16-step (rows are 128B)
    uint32_t kbs[4];
#pragma unroll
    for (int k = 0; k < 4; k++)
        kbs[k] = (uint32_t)((k * 32 + hi * 16) ^ ((lane & 7) * 16));
    uint32_t rowA[4], rowB[4];
#pragma unroll
    for (int mf = 0; mf < 4; mf++) rowA[mf] = (uint32_t)(wm * 64 + mf * 16 + l15) * 128u;
#pragma unroll
    for (int nfp = 0; nfp < 4; nfp++) rowB[nfp] = (uint32_t)(wn * 64 + nfp * 16 + l15) * 128u;

    float d[4][8][4];
#pragma unroll
    for (int mf = 0; mf < 4; mf++)
#pragma unroll
        for (int nf = 0; nf < 8; nf++)
#pragma unroll
            for (int r = 0; r < 4; r++) d[mf][nf][r] = 0.f;

    const char* gA = (const char*)g_A;
    const char* gB = (const char*)g_B;

    auto issue = [&](int c) {
        int seg = c / 10, cc = c - seg * 10;
        int p = c & (NSTAGE_ - 1);
        size_t baA = ((size_t)(b * 2 + c_mapA[seg]) * ROWSPB_ + rbase) * (C_ * 2)
                     + (size_t)cc * 128;
        size_t baB = ((size_t)(b * 2 + c_mapB[seg]) * CPAD_ + cb * 256) * (C_ * 2)
                     + (size_t)cc * 128;
#pragma unroll
        for (int i = 0; i < 4; i++) {      // A: 128 rows x 8 granules
            int g = tid + 256 * i;
            int r = g >> 3; uint32_t c16 = (uint32_t)(g & 7) * 16;
            cpa16(aA[p] + (uint32_t)r * 128 + (c16 ^ ((uint32_t)(r & 7) * 16)),
                  gA + baA + (size_t)r * (C_ * 2) + c16);
        }
#pragma unroll
        for (int i = 0; i < 8; i++) {      // B: 256 rows x 8 granules
            int g = tid + 256 * i;
            int r = g >> 3; uint32_t c16 = (uint32_t)(g & 7) * 16;
            cpa16(aB[p] + (uint32_t)r * 128 + (c16 ^ ((uint32_t)(r & 7) * 16)),
                  gB + baB + (size_t)r * (C_ * 2) + c16);
        }
        asm volatile("cp.async.commit_group;");
    };

    // prologue: 3 chunks in flight
    issue(0); issue(1); issue(2);

    for (int c = 0; c < NCHUNK_; c++) {
        if (c <= NCHUNK_ - 3)      asm volatile("cp.async.wait_group 2;");
        else if (c == NCHUNK_ - 2) asm volatile("cp.async.wait_group 1;");
        else                       asm volatile("cp.async.wait_group 0;");
        __syncthreads();

        if (c + 3 < NCHUNK_) issue(c + 3);

        const int p = c & (NSTAGE_ - 1);

        // ks-pipelined mainloop: preload fragments for ks+1 during hmma of ks
        uint32_t afr[2][4][4], bfr[2][4][4];
#pragma unroll
        for (int mf = 0; mf < 4; mf++) ldsm4(afr[0][mf], aA[p] + rowA[mf] + kbs[0]);
#pragma unroll
        for (int nfp = 0; nfp < 4; nfp++) ldsm4(bfr[0][nfp], aB[p] + rowB[nfp] + kbs[0]);

#pragma unroll
        for (int ks = 0; ks < 4; ks++) {
            const int cur = ks & 1, nx = cur ^ 1;
            if (ks < 3) {
#pragma unroll
                for (int mf = 0; mf < 4; mf++)
                    ldsm4(afr[nx][mf], aA[p] + rowA[mf] + kbs[ks + 1]);
#pragma unroll
                for (int nfp = 0; nfp < 4; nfp++)
                    ldsm4(bfr[nx][nfp], aB[p] + rowB[nfp] + kbs[ks + 1]);
            }
#pragma unroll
            for (int mf = 0; mf < 4; mf++)
#pragma unroll
                for (int nf = 0; nf < 8; nf++)
                    hmma16(d[mf][nf], afr[cur][mf],
                           bfr[cur][nf >> 1][nf & 1], bfr[cur][nf >> 1][(nf & 1) + 2]);
        }
    }
    __syncthreads();   // all warps done with last stage before smem reuse

    // ---- epilogue: single-pass 128x256 through smem, parallel reduction ----
#pragma unroll
    for (int mf = 0; mf < 4; mf++)
#pragma unroll
        for (int nf = 0; nf < 8; nf++) {
            int row = wm * 64 + mf * 16 + (lane >> 2);
            int coll = wn * 64 + nf * 8 + (lane & 3) * 2;
            smSD[row * SDSTR_ + coll]           = d[mf][nf][0];
            smSD[row * SDSTR_ + coll + 1]       = d[mf][nf][1];
            smSD[(row + 8) * SDSTR_ + coll]     = d[mf][nf][2];
            smSD[(row + 8) * SDSTR_ + coll + 1] = d[mf][nf][3];
        }
    __syncthreads();

    {
        const int row = tid >> 1, sub = tid & 1;   // 2 reducers per row, halves
        const int rg = rbase + row;                 // always < ROWS_R
        const int q = rg / M_, m = rg - q * M_;
        const float qiv = g_qinv[(b * Q_ + q) * M_ + m];

        float cmax[NW_];
#pragma unroll
        for (int w = 0; w < NW_; w++) cmax[w] = -FLT_MAX;
        float gv = -FLT_MAX;
        int gi = 0x7FFFFFFF;

        const float* rowp = smSD + row * SDSTR_ + sub * 128;
        const float* sinp = sSinv + sub * 128;
        const int colg0 = cb * 256 + sub * 128;

        // 32 float4 groups; 500 and 2500 are multiples of 4 -> class id and
        // validity are constant within each aligned group.
        for (int i = 0; i < 32; i++) {
            int colg = colg0 + 4 * i;
            if (colg < COLS_) {
                float4 vv = *(const float4*)(rowp + 4 * i);
                float4 sv = *(const float4*)(sinp + 4 * i);
                float v0 = vv.x * qiv * sv.x;
                float v1 = vv.y * qiv * sv.y;
                float v2 = vv.z * qiv * sv.z;
                float v3 = vv.w * qiv * sv.w;
                float bv = v0; int bo = 0;
                if (v1 > bv) { bv = v1; bo = 1; }
                if (v2 > bv) { bv = v2; bo = 2; }
                if (v3 > bv) { bv = v3; bo = 3; }
                int cls = colg / MS_;
                if (bv > cmax[cls]) cmax[cls] = bv;
                if (bv > gv) { gv = bv; gi = colg + bo; }  // ascending scan
            }
        }
        // merge halves (partition-independent first-index semantics)
#pragma unroll
        for (int w = 0; w < NW_; w++) {
            float o = __shfl_xor_sync(0xFFFFFFFFu, cmax[w], 1);
            cmax[w] = fmaxf(cmax[w], o);
        }
        float ogv = __shfl_xor_sync(0xFFFFFFFFu, gv, 1);
        int   ogi = __shfl_xor_sync(0xFFFFFFFFu, gi, 1);
        if (ogv > gv || (ogv == gv && ogi < gi)) { gv = ogv; gi = ogi; }

        if (sub == 0) {
            size_t pr = ((size_t)b * ROWSPB_ + rg) * CB_ + cb;
#pragma unroll
            for (int w = 0; w < NW_; w++) g_pcm[pr * NW_ + w] = cmax[w];
            g_pgv[pr] = gv;
            g_pgi[pr] = gi;
        }
    }
}

// ---------------------------------------------------------------------------
// Merge partials + mutual-nearest mask + predict (one block per (b,q)),
// with the final loss fused via the last-block threadfence pattern.
// ---------------------------------------------------------------------------
__global__ __launch_bounds__(128) void mask_k(const int* __restrict__ qy,
                                              float* __restrict__ out) {
    const int bq = blockIdx.x;
    const int b = bq / Q_;
    const int tid = threadIdx.x;

    __shared__ float sCm[M_][NW_];
    __shared__ float sDiff[M_];
    __shared__ int   sNear[M_];
    __shared__ float sMask[M_];
    __shared__ int   sLast;
    __shared__ float sPart[128];

    if (tid < M_) {
        int rg = (bq % Q_) * M_ + tid;
        size_t basep = ((size_t)b * ROWSPB_ + rg) * CB_;
        float cm[NW_];
#pragma unroll
        for (int w = 0; w < NW_; w++) cm[w] = -FLT_MAX;
        float gv = -FLT_MAX;
        int gi = 0;
        for (int t = 0; t < CB_; t++) {          // ascending col-block order
            size_t p = basep + t;
#pragma unroll
            for (int w = 0; w < NW_; w++) {
                float v = g_pcm[p * NW_ + w];
                if (v > cm[w]) cm[w] = v;
            }
            float v = g_pgv[p];
            if (v > gv) { gv = v; gi = g_pgi[p]; }
        }
        float m1 = -FLT_MAX, m2 = -FLT_MAX;
#pragma unroll
        for (int w = 0; w < NW_; w++) {
            float v = cm[w];
            if (v > m1) { m2 = m1; m1 = v; }
            else if (v > m2) { m2 = v; }
            sCm[tid][w] = v;
        }
        sDiff[tid] = m1 - m2;
        sNear[tid] = gi;
    }
    __syncthreads();

    if (tid < M_) {
        int slot = sNear[tid];
        float best = -1.0f;
        int idx = -1;
        for (int mp = 0; mp < M_; mp++) {
            float v = (sNear[mp] == slot) ? sDiff[mp] : 0.0f;
            if (v > best) { best = v; idx = mp; }
        }
        sMask[tid] = (idx == tid) ? TEMP_ : 0.0f;
    }
    __syncthreads();

    if (tid < NW_) {
        float p = 0.f;
        for (int m = 0; m < M_; m++)
            p += sCm[m][tid] * sMask[m];
        g_pred[bq * NW_ + tid] = p;
    }

    // ---- last block computes the loss (deterministic tree reduction) ----
    __threadfence();
    __syncthreads();
    if (tid == 0) {
        int c = atomicAdd(&g_cnt, 1);
        sLast = (c == BQ_ - 1) ? 1 : 0;
    }
    __syncthreads();
    if (sLast) {
        __threadfence();
        float v = 0.f;
        for (int t = tid; t < BQ_; t += 128) {     // fixed order per thread
            const float* p = g_pred + t * NW_;
            float mx = p[0];
#pragma unroll
            for (int w = 1; w < NW_; w++) mx = fmaxf(mx, p[w]);
            float se = 0.f;
#pragma unroll
            for (int w = 0; w < NW_; w++) se += expf(p[w] - mx);
            float lse = mx + logf(se);
            v += p[qy[t]] - lse;
        }
        sPart[tid] = v;
        __syncthreads();
        for (int s = 64; s > 0; s >>= 1) {
            if (tid < s) sPart[tid] += sPart[tid + s];
            __syncthreads();
        }
        if (tid == 0) {
            out[0] = -sPart[0] / (float)BQ_;
            g_cnt = 0;                              // reset for next replay
        }
    }
}

// ---------------------------------------------------------------------------
extern "C" void kernel_launch(void* const* d_in, const int* in_sizes, int n_in,
                              void* d_out, int out_size)
{
    const float* support_xf = (const float*)d_in[0];   // [4,25,640,100]
    const float* query_xf   = (const float*)d_in[2];   // [4,75,640,100]
    const int*   query_y    = (const int*)d_in[3];     // [4,75]
    float* out = (float*)d_out;

    cudaFuncSetAttribute(mma_gemm_k, cudaFuncAttributeMaxDynamicSharedMemorySize,
                         NSTAGE_ * 49152);

    convAB_k<<<dim3(10, NENT_), 256>>>(query_xf, support_xf);
    normfin_k<<<NENT_, 128>>>();
    mma_gemm_k<<<dim3(590, 1, B_), 256, NSTAGE_ * 49152>>>();
    mask_k<<<BQ_, 128>>>(query_y, out);
}